// round 4
// baseline (speedup 1.0000x reference)
#include <cuda_runtime.h>
#include <cstdint>

#define NNODES 50000
#define NEDGES 1600000
#define CMAX 256
#define EPS 1e-5f

// ----------------------------- scratch (static device memory, no allocs) ----
__device__ __align__(16) float g_scr[(size_t)NNODES * CMAX];   // buf 0
__device__ __align__(16) float g_pre[(size_t)NNODES * CMAX];   // buf 1 (BN input)
__device__ __align__(16) float g_actA[(size_t)NNODES * CMAX];  // buf 2
__device__ __align__(16) float g_actB[(size_t)NNODES * CMAX];  // buf 3
__device__ float g_deg[NNODES];
__device__ float g_dinv[NNODES];
__device__ float g_dinv2[NNODES];
__device__ int   g_src[NEDGES];
__device__ int   g_dst[NEDGES];
__device__ float g_norm[NEDGES];
__device__ float g_sum[CMAX];
__device__ float g_ss[CMAX];
__device__ float g_scale[CMAX];
__device__ float g_shift[CMAX];
__device__ int   g_is64;

__device__ __forceinline__ float* scratch(int b) {
    return (b == 0) ? g_scr : (b == 1) ? g_pre : (b == 2) ? g_actA : g_actB;
}

// ----------------------------- dtype detection ------------------------------
// edge_index may be int32 (JAX default, x64 disabled) or int64. Read the first
// 64 values as int64 (bytes 0..511 — safe under either dtype since the buffer
// holds >= 12.8MB) and range-check. int32 data read as int64 fuses two indices
// into lo + hi*2^32, which is out of [0, NNODES) unless hi==0 (p ~= 2e-5).
__global__ void k_detect(const void* __restrict__ ei) {
    if (threadIdx.x == 0 && blockIdx.x == 0) {
        const long long* p = (const long long*)ei;
        int ok = 1;
        for (int i = 0; i < 64; i++) {
            long long v = p[i];
            if (v < 0 || v >= NNODES) { ok = 0; break; }
        }
        g_is64 = ok;
    }
}

__device__ __forceinline__ void load_edge(const void* __restrict__ ei, int e, int& s, int& d) {
    if (g_is64) {
        const long long* p = (const long long*)ei;
        s = (int)p[e];
        d = (int)p[(size_t)NEDGES + e];
    } else {
        const int* p = (const int*)ei;
        s = p[e];
        d = p[(size_t)NEDGES + e];
    }
}

// ----------------------------- prep kernels ---------------------------------
__global__ void k_deg_init() {
    int i = blockIdx.x * blockDim.x + threadIdx.x;
    if (i < NNODES) g_deg[i] = 1.0f;   // self-loop weight
}

__global__ void k_deg_acc(const void* __restrict__ ei, const float* __restrict__ ew) {
    int e = blockIdx.x * blockDim.x + threadIdx.x;
    if (e < NEDGES) {
        int s, d;
        load_edge(ei, e, s, d);
        atomicAdd(&g_deg[d], ew[e]);
    }
}

__global__ void k_dinv() {
    int i = blockIdx.x * blockDim.x + threadIdx.x;
    if (i < NNODES) {
        float d = g_deg[i];
        g_dinv[i]  = rsqrtf(d);
        g_dinv2[i] = 1.0f / d;
    }
}

__global__ void k_edge_prep(const void* __restrict__ ei, const float* __restrict__ ew) {
    int e = blockIdx.x * blockDim.x + threadIdx.x;
    if (e < NEDGES) {
        int s, d;
        load_edge(ei, e, s, d);
        g_src[e] = s;
        g_dst[e] = d;
        g_norm[e] = g_dinv[s] * ew[e] * g_dinv[d];
    }
}

// ----------------------------- aggregation ----------------------------------
// out[i] = in[i] * dinv2[i]   (self-loop term; also initializes the accumulator)
template<int C>
__global__ void k_self_init(const float* __restrict__ in_ext, int in_buf, int out_buf) {
    constexpr int SH = (C == 64) ? 6 : (C == 128) ? 7 : 8;
    const float* in = in_ext ? in_ext : scratch(in_buf);
    float* out = scratch(out_buf);
    long long t = (long long)blockIdx.x * blockDim.x + threadIdx.x;
    if (t < (long long)NNODES * C) {
        int i = (int)(t >> SH);
        out[t] = in[t] * g_dinv2[i];
    }
}

// out[dst] += norm * h[src]; one thread per (edge, 4-channel group), scalar atomics
template<int C4>
__global__ void k_edge_agg(const float* __restrict__ h_ext, int h_buf, int out_buf) {
    constexpr int SH = (C4 == 16) ? 4 : (C4 == 32) ? 5 : 6;
    const float* h = h_ext ? h_ext : scratch(h_buf);
    float* out = scratch(out_buf);
    long long t = (long long)blockIdx.x * blockDim.x + threadIdx.x;
    if (t >= (long long)NEDGES * C4) return;
    int e  = (int)(t >> SH);
    int c4 = (int)(t & (C4 - 1));
    int s = g_src[e];
    int d = g_dst[e];
    float w = g_norm[e];
    const float4* h4 = (const float4*)h;
    float4 v = h4[(size_t)s * C4 + c4];
    float* addr = out + ((size_t)d * C4 + c4) * 4;
    atomicAdd(addr + 0, v.x * w);
    atomicAdd(addr + 1, v.y * w);
    atomicAdd(addr + 2, v.z * w);
    atomicAdd(addr + 3, v.w * w);
}

// ----------------------------- SGEMM ----------------------------------------
// C[N, Ncols] = A[N, K] @ B[K, Ncols]; BM=128, BN=64, BK=16, 256 threads, 8x4 microtile
#define GBM 128
#define GBN 64
#define GBK 16
__global__ __launch_bounds__(256) void k_gemm(const float* __restrict__ A_ext, int A_buf,
                                              const float* __restrict__ B,
                                              int C_buf,
                                              int Nrows, int K, int Ncols) {
    const float* A = A_ext ? A_ext : scratch(A_buf);
    float* Cmat = scratch(C_buf);
    __shared__ float As[GBK][GBM + 4];
    __shared__ float Bs[GBK][GBN];
    int bm = blockIdx.x * GBM;
    int bn = blockIdx.y * GBN;
    int tid = threadIdx.x;
    int tx = tid & 15;   // column group (4 cols each)
    int ty = tid >> 4;   // row group (8 rows each)

    float acc[8][4];
#pragma unroll
    for (int i = 0; i < 8; i++)
#pragma unroll
        for (int j = 0; j < 4; j++) acc[i][j] = 0.0f;

    for (int k0 = 0; k0 < K; k0 += GBK) {
        // A tile: 128 rows x 16 k = 512 float4; 2 per thread
#pragma unroll
        for (int l = 0; l < 2; l++) {
            int idx = tid * 2 + l;
            int r  = idx >> 2;
            int kq = idx & 3;
            int grow = bm + r;
            float4 v = make_float4(0.f, 0.f, 0.f, 0.f);
            if (grow < Nrows)
                v = *((const float4*)(A + (size_t)grow * K + k0 + kq * 4));
            As[kq * 4 + 0][r] = v.x;
            As[kq * 4 + 1][r] = v.y;
            As[kq * 4 + 2][r] = v.z;
            As[kq * 4 + 3][r] = v.w;
        }
        // B tile: 16 k x 64 cols = 256 float4; 1 per thread
        {
            int r  = tid >> 4;
            int cq = tid & 15;
            float4 v = *((const float4*)(B + (size_t)(k0 + r) * Ncols + bn + cq * 4));
            *((float4*)&Bs[r][cq * 4]) = v;
        }
        __syncthreads();
#pragma unroll
        for (int k = 0; k < GBK; k++) {
            float a[8], b[4];
#pragma unroll
            for (int i = 0; i < 8; i++) a[i] = As[k][ty * 8 + i];
#pragma unroll
            for (int j = 0; j < 4; j++) b[j] = Bs[k][tx * 4 + j];
#pragma unroll
            for (int i = 0; i < 8; i++)
#pragma unroll
                for (int j = 0; j < 4; j++) acc[i][j] = fmaf(a[i], b[j], acc[i][j]);
        }
        __syncthreads();
    }
#pragma unroll
    for (int i = 0; i < 8; i++) {
        int grow = bm + ty * 8 + i;
        if (grow < Nrows) {
            float4 v = make_float4(acc[i][0], acc[i][1], acc[i][2], acc[i][3]);
            *((float4*)(Cmat + (size_t)grow * Ncols + bn + tx * 4)) = v;
        }
    }
}

// ----------------------------- BatchNorm ------------------------------------
// BN input is always g_pre (buf 1).
__global__ void k_zero_stats() {
    int c = threadIdx.x;
    g_sum[c] = 0.0f;
    g_ss[c] = 0.0f;
}

__global__ void k_bn_stats(int C) {
    int c = threadIdx.x;           // blockDim.x == C
    int r0 = blockIdx.x * 128;
    int rend = min(r0 + 128, NNODES);
    float s = 0.0f, ss = 0.0f;
    for (int r = r0; r < rend; r++) {
        float v = g_pre[(size_t)r * C + c];
        s += v;
        ss = fmaf(v, v, ss);
    }
    atomicAdd(&g_sum[c], s);
    atomicAdd(&g_ss[c], ss);
}

__global__ void k_bn_final(const float* __restrict__ g, const float* __restrict__ bb, int C) {
    int c = threadIdx.x;
    if (c < C) {
        float mean = g_sum[c] * (1.0f / NNODES);
        float var  = g_ss[c] * (1.0f / NNODES) - mean * mean;
        float sc = g[c] * rsqrtf(var + EPS);
        g_scale[c] = sc;
        g_shift[c] = bb[c] - mean * sc;
    }
}

template<int C, bool RELU>
__global__ void k_bn_apply(float* __restrict__ out_ext, int out_buf) {
    float* out = out_ext ? out_ext : scratch(out_buf);
    long long t = (long long)blockIdx.x * blockDim.x + threadIdx.x;
    if (t < (long long)NNODES * C) {
        int c = (int)(t & (C - 1));
        float y = fmaf(g_pre[t], g_scale[c], g_shift[c]);
        if (RELU) y = fmaxf(y, 0.0f);
        out[t] = y;
    }
}

// ----------------------------- dispatch helpers ------------------------------
static void launch_self_init(const float* in_ext, int in_buf, int out_buf, int C, cudaStream_t st) {
    long long total = (long long)NNODES * C;
    int blocks = (int)((total + 255) / 256);
    switch (C) {
        case 64:  k_self_init<64> <<<blocks, 256, 0, st>>>(in_ext, in_buf, out_buf); break;
        case 128: k_self_init<128><<<blocks, 256, 0, st>>>(in_ext, in_buf, out_buf); break;
        case 256: k_self_init<256><<<blocks, 256, 0, st>>>(in_ext, in_buf, out_buf); break;
    }
}

static void launch_edge_agg(const float* h_ext, int h_buf, int out_buf, int C, cudaStream_t st) {
    int C4 = C / 4;
    long long total = (long long)NEDGES * C4;
    int blocks = (int)((total + 255) / 256);
    switch (C4) {
        case 16: k_edge_agg<16><<<blocks, 256, 0, st>>>(h_ext, h_buf, out_buf); break;
        case 32: k_edge_agg<32><<<blocks, 256, 0, st>>>(h_ext, h_buf, out_buf); break;
        case 64: k_edge_agg<64><<<blocks, 256, 0, st>>>(h_ext, h_buf, out_buf); break;
    }
}

static void launch_bn_apply(float* out_ext, int out_buf, int C, bool relu, cudaStream_t st) {
    long long total = (long long)NNODES * C;
    int blocks = (int)((total + 255) / 256);
    if (relu) {
        switch (C) {
            case 64:  k_bn_apply<64, true> <<<blocks, 256, 0, st>>>(out_ext, out_buf); break;
            case 128: k_bn_apply<128, true><<<blocks, 256, 0, st>>>(out_ext, out_buf); break;
            case 256: k_bn_apply<256, true><<<blocks, 256, 0, st>>>(out_ext, out_buf); break;
        }
    } else {
        switch (C) {
            case 64:  k_bn_apply<64, false> <<<blocks, 256, 0, st>>>(out_ext, out_buf); break;
            case 128: k_bn_apply<128, false><<<blocks, 256, 0, st>>>(out_ext, out_buf); break;
            case 256: k_bn_apply<256, false><<<blocks, 256, 0, st>>>(out_ext, out_buf); break;
        }
    }
}

// ----------------------------- entry ----------------------------------------
extern "C" void kernel_launch(void* const* d_in, const int* in_sizes, int n_in,
                              void* d_out, int out_size) {
    (void)in_sizes; (void)n_in; (void)out_size;
    cudaStream_t st = 0;

    const float* x  = (const float*)d_in[0];
    const void*  ei = d_in[1];
    const float* ew = (const float*)d_in[2];
    float* out = (float*)d_out;

    // prep: dtype detection + degrees + normalized edge weights
    k_detect<<<1, 32, 0, st>>>(ei);
    k_deg_init<<<(NNODES + 255) / 256, 256, 0, st>>>();
    k_deg_acc<<<(NEDGES + 255) / 256, 256, 0, st>>>(ei, ew);
    k_dinv<<<(NNODES + 255) / 256, 256, 0, st>>>();
    k_edge_prep<<<(NEDGES + 255) / 256, 256, 0, st>>>(ei, ew);

    const int Cs[6] = {128, 64, 128, 256, 256, 128};
    const float* cur_ext = x;   // external pointer for layer input (x), else nullptr
    int cur_buf = -1;

    for (int li = 0; li < 5; li++) {
        int Cin = Cs[li], Cout = Cs[li + 1];
        const float* W  = (const float*)d_in[3 + 4 * li];
        const float* g  = (const float*)d_in[5 + 4 * li];
        const float* bb = (const float*)d_in[6 + 4 * li];

        dim3 grid((NNODES + GBM - 1) / GBM, Cout / GBN);
        if (Cin <= Cout) {
            // aggregate first (cheaper dim) into buf0, then GEMM -> buf1 (g_pre)
            launch_self_init(cur_ext, cur_buf, 0, Cin, st);
            launch_edge_agg(cur_ext, cur_buf, 0, Cin, st);
            k_gemm<<<grid, 256, 0, st>>>(nullptr, 0, W, 1, NNODES, Cin, Cout);
        } else {
            // GEMM -> buf0, then aggregate (smaller output dim) -> buf1 (g_pre)
            k_gemm<<<grid, 256, 0, st>>>(cur_ext, cur_buf, W, 0, NNODES, Cin, Cout);
            launch_self_init(nullptr, 0, 1, Cout, st);
            launch_edge_agg(nullptr, 0, 1, Cout, st);
        }

        // BatchNorm (+ ReLU except last layer). Bias b cancels under BN -> skipped.
        k_zero_stats<<<1, CMAX, 0, st>>>();
        k_bn_stats<<<(NNODES + 127) / 128, Cout, 0, st>>>(Cout);
        k_bn_final<<<1, CMAX, 0, st>>>(g, bb, Cout);

        int act_buf = (li & 1) ? 3 : 2;
        if (li == 4) launch_bn_apply(out, -1, Cout, false, st);
        else         launch_bn_apply(nullptr, act_buf, Cout, true, st);

        cur_ext = nullptr;
        cur_buf = act_buf;
    }
}

// round 5
// speedup vs baseline: 3.0898x; 3.0898x over previous
#include <cuda_runtime.h>
#include <cstdint>

#define NNODES 50000
#define NEDGES 1600000
#define CMAX 256
#define EPS 1e-5f

// ----------------------------- scratch (static device memory, no allocs) ----
__device__ __align__(16) float g_scr[(size_t)NNODES * CMAX];   // buf 0
__device__ __align__(16) float g_pre[(size_t)NNODES * CMAX];   // buf 1 (BN input)
__device__ __align__(16) float g_actA[(size_t)NNODES * CMAX];  // buf 2
__device__ __align__(16) float g_actB[(size_t)NNODES * CMAX];  // buf 3
__device__ float g_deg[NNODES];
__device__ float g_dinv[NNODES];
__device__ float g_dinv2[NNODES];
__device__ int   g_cnt[NNODES];          // per-dst edge histogram
__device__ int   g_fill[NNODES];         // CSR fill cursors
__device__ int   g_rowptr[NNODES + 1];   // CSR row pointers (by dst)
__device__ __align__(8) float2 g_csr[NEDGES];  // {src (int bits), normalized weight}
__device__ float g_sum[CMAX];
__device__ float g_ss[CMAX];
__device__ float g_scale[CMAX];
__device__ float g_shift[CMAX];
__device__ int   g_is64;

__device__ __forceinline__ float* scratch(int b) {
    return (b == 0) ? g_scr : (b == 1) ? g_pre : (b == 2) ? g_actA : g_actB;
}

// ----------------------------- dtype detection ------------------------------
// edge_index may be int32 (JAX default) or int64. Range-check first 64 values
// read as int64: int32 data fuses pairs into lo + hi*2^32 -> out of range.
__global__ void k_detect(const void* __restrict__ ei) {
    if (threadIdx.x == 0 && blockIdx.x == 0) {
        const long long* p = (const long long*)ei;
        int ok = 1;
        for (int i = 0; i < 64; i++) {
            long long v = p[i];
            if (v < 0 || v >= NNODES) { ok = 0; break; }
        }
        g_is64 = ok;
    }
}

__device__ __forceinline__ void load_edge(const void* __restrict__ ei, int e, int& s, int& d) {
    if (g_is64) {
        const long long* p = (const long long*)ei;
        s = (int)p[e];
        d = (int)p[(size_t)NEDGES + e];
    } else {
        const int* p = (const int*)ei;
        s = p[e];
        d = p[(size_t)NEDGES + e];
    }
}

// ----------------------------- prep kernels ---------------------------------
__global__ void k_init_nodes() {
    int i = blockIdx.x * blockDim.x + threadIdx.x;
    if (i < NNODES) {
        g_deg[i] = 1.0f;   // self-loop weight
        g_cnt[i] = 0;
        g_fill[i] = 0;
    }
}

// degree accumulation + dst histogram in one pass
__global__ void k_deg_hist(const void* __restrict__ ei, const float* __restrict__ ew) {
    int e = blockIdx.x * blockDim.x + threadIdx.x;
    if (e < NEDGES) {
        int s, d;
        load_edge(ei, e, s, d);
        atomicAdd(&g_deg[d], ew[e]);
        atomicAdd(&g_cnt[d], 1);
    }
}

__global__ void k_dinv() {
    int i = blockIdx.x * blockDim.x + threadIdx.x;
    if (i < NNODES) {
        float d = g_deg[i];
        g_dinv[i]  = rsqrtf(d);
        g_dinv2[i] = 1.0f / d;
    }
}

// single-block inclusive scan of g_cnt -> g_rowptr[1..N], rowptr[0]=0
__global__ void k_scan() {
    __shared__ int sh[1024];
    __shared__ int carry_s;
    int tid = threadIdx.x;
    if (tid == 0) carry_s = 0;
    __syncthreads();
    for (int base = 0; base < NNODES; base += 1024) {
        int i = base + tid;
        int v = (i < NNODES) ? g_cnt[i] : 0;
        sh[tid] = v;
        __syncthreads();
        for (int off = 1; off < 1024; off <<= 1) {
            int t = (tid >= off) ? sh[tid - off] : 0;
            __syncthreads();
            sh[tid] += t;
            __syncthreads();
        }
        if (i < NNODES) g_rowptr[i + 1] = carry_s + sh[tid];
        __syncthreads();
        if (tid == 1023) carry_s += sh[1023];
        __syncthreads();
    }
    if (tid == 0) g_rowptr[0] = 0;
}

// compute normalized weights + scatter edges into CSR (grouped by dst)
__global__ void k_fill(const void* __restrict__ ei, const float* __restrict__ ew) {
    int e = blockIdx.x * blockDim.x + threadIdx.x;
    if (e < NEDGES) {
        int s, d;
        load_edge(ei, e, s, d);
        float w = g_dinv[s] * ew[e] * g_dinv[d];
        int pos = g_rowptr[d] + atomicAdd(&g_fill[d], 1);
        g_csr[pos] = make_float2(__int_as_float(s), w);
    }
}

// ----------------------------- aggregation (gather, no atomics) -------------
// out[i] = in[i]*dinv2[i] + sum_{e in row i} w_e * in[src_e]
// One C4-lane group per node; lane owns one float4 channel group.
template<int C4>
__global__ __launch_bounds__(256) void k_agg(const float* __restrict__ in_ext, int in_buf, int out_buf) {
    constexpr int NPB = 256 / C4;
    const float4* in = (const float4*)(in_ext ? in_ext : scratch(in_buf));
    float4* out = (float4*)scratch(out_buf);
    int node = blockIdx.x * NPB + threadIdx.x / C4;
    int lane = threadIdx.x & (C4 - 1);
    if (node >= NNODES) return;

    float di2 = g_dinv2[node];
    float4 self = in[(size_t)node * C4 + lane];
    float4 acc = make_float4(self.x * di2, self.y * di2, self.z * di2, self.w * di2);

    int beg = g_rowptr[node];
    int end = g_rowptr[node + 1];
    for (int e = beg; e < end; e++) {
        float2 sw = g_csr[e];
        int s = __float_as_int(sw.x);
        float w = sw.y;
        float4 v = in[(size_t)s * C4 + lane];
        acc.x = fmaf(w, v.x, acc.x);
        acc.y = fmaf(w, v.y, acc.y);
        acc.z = fmaf(w, v.z, acc.z);
        acc.w = fmaf(w, v.w, acc.w);
    }
    out[(size_t)node * C4 + lane] = acc;
}

// ----------------------------- SGEMM ----------------------------------------
// C[N, Ncols] = A[N, K] @ B[K, Ncols]; BM=128, BN=64, BK=16, 256 threads, 8x4 microtile
#define GBM 128
#define GBN 64
#define GBK 16
__global__ __launch_bounds__(256) void k_gemm(const float* __restrict__ A_ext, int A_buf,
                                              const float* __restrict__ B,
                                              int C_buf,
                                              int Nrows, int K, int Ncols) {
    const float* A = A_ext ? A_ext : scratch(A_buf);
    float* Cmat = scratch(C_buf);
    __shared__ float As[GBK][GBM + 4];
    __shared__ float Bs[GBK][GBN];
    int bm = blockIdx.x * GBM;
    int bn = blockIdx.y * GBN;
    int tid = threadIdx.x;
    int tx = tid & 15;   // column group (4 cols each)
    int ty = tid >> 4;   // row group (8 rows each)

    float acc[8][4];
#pragma unroll
    for (int i = 0; i < 8; i++)
#pragma unroll
        for (int j = 0; j < 4; j++) acc[i][j] = 0.0f;

    for (int k0 = 0; k0 < K; k0 += GBK) {
#pragma unroll
        for (int l = 0; l < 2; l++) {
            int idx = tid * 2 + l;
            int r  = idx >> 2;
            int kq = idx & 3;
            int grow = bm + r;
            float4 v = make_float4(0.f, 0.f, 0.f, 0.f);
            if (grow < Nrows)
                v = *((const float4*)(A + (size_t)grow * K + k0 + kq * 4));
            As[kq * 4 + 0][r] = v.x;
            As[kq * 4 + 1][r] = v.y;
            As[kq * 4 + 2][r] = v.z;
            As[kq * 4 + 3][r] = v.w;
        }
        {
            int r  = tid >> 4;
            int cq = tid & 15;
            float4 v = *((const float4*)(B + (size_t)(k0 + r) * Ncols + bn + cq * 4));
            *((float4*)&Bs[r][cq * 4]) = v;
        }
        __syncthreads();
#pragma unroll
        for (int k = 0; k < GBK; k++) {
            float a[8], b[4];
#pragma unroll
            for (int i = 0; i < 8; i++) a[i] = As[k][ty * 8 + i];
#pragma unroll
            for (int j = 0; j < 4; j++) b[j] = Bs[k][tx * 4 + j];
#pragma unroll
            for (int i = 0; i < 8; i++)
#pragma unroll
                for (int j = 0; j < 4; j++) acc[i][j] = fmaf(a[i], b[j], acc[i][j]);
        }
        __syncthreads();
    }
#pragma unroll
    for (int i = 0; i < 8; i++) {
        int grow = bm + ty * 8 + i;
        if (grow < Nrows) {
            float4 v = make_float4(acc[i][0], acc[i][1], acc[i][2], acc[i][3]);
            *((float4*)(Cmat + (size_t)grow * Ncols + bn + tx * 4)) = v;
        }
    }
}

// ----------------------------- BatchNorm ------------------------------------
__global__ void k_zero_stats() {
    int c = threadIdx.x;
    g_sum[c] = 0.0f;
    g_ss[c] = 0.0f;
}

__global__ void k_bn_stats(int C) {
    int c = threadIdx.x;           // blockDim.x == C
    int r0 = blockIdx.x * 128;
    int rend = min(r0 + 128, NNODES);
    float s = 0.0f, ss = 0.0f;
    for (int r = r0; r < rend; r++) {
        float v = g_pre[(size_t)r * C + c];
        s += v;
        ss = fmaf(v, v, ss);
    }
    atomicAdd(&g_sum[c], s);
    atomicAdd(&g_ss[c], ss);
}

__global__ void k_bn_final(const float* __restrict__ g, const float* __restrict__ bb, int C) {
    int c = threadIdx.x;
    if (c < C) {
        float mean = g_sum[c] * (1.0f / NNODES);
        float var  = g_ss[c] * (1.0f / NNODES) - mean * mean;
        float sc = g[c] * rsqrtf(var + EPS);
        g_scale[c] = sc;
        g_shift[c] = bb[c] - mean * sc;
    }
}

template<int C, bool RELU>
__global__ void k_bn_apply(float* __restrict__ out_ext, int out_buf) {
    float* out = out_ext ? out_ext : scratch(out_buf);
    long long t = (long long)blockIdx.x * blockDim.x + threadIdx.x;
    if (t < (long long)NNODES * C) {
        int c = (int)(t & (C - 1));
        float y = fmaf(g_pre[t], g_scale[c], g_shift[c]);
        if (RELU) y = fmaxf(y, 0.0f);
        out[t] = y;
    }
}

// ----------------------------- dispatch helpers ------------------------------
static void launch_agg(const float* in_ext, int in_buf, int out_buf, int C, cudaStream_t st) {
    int C4 = C / 4;
    int npb = 256 / C4;
    int blocks = (NNODES + npb - 1) / npb;
    switch (C4) {
        case 16: k_agg<16><<<blocks, 256, 0, st>>>(in_ext, in_buf, out_buf); break;
        case 32: k_agg<32><<<blocks, 256, 0, st>>>(in_ext, in_buf, out_buf); break;
        case 64: k_agg<64><<<blocks, 256, 0, st>>>(in_ext, in_buf, out_buf); break;
    }
}

static void launch_bn_apply(float* out_ext, int out_buf, int C, bool relu, cudaStream_t st) {
    long long total = (long long)NNODES * C;
    int blocks = (int)((total + 255) / 256);
    if (relu) {
        switch (C) {
            case 64:  k_bn_apply<64, true> <<<blocks, 256, 0, st>>>(out_ext, out_buf); break;
            case 128: k_bn_apply<128, true><<<blocks, 256, 0, st>>>(out_ext, out_buf); break;
            case 256: k_bn_apply<256, true><<<blocks, 256, 0, st>>>(out_ext, out_buf); break;
        }
    } else {
        switch (C) {
            case 64:  k_bn_apply<64, false> <<<blocks, 256, 0, st>>>(out_ext, out_buf); break;
            case 128: k_bn_apply<128, false><<<blocks, 256, 0, st>>>(out_ext, out_buf); break;
            case 256: k_bn_apply<256, false><<<blocks, 256, 0, st>>>(out_ext, out_buf); break;
        }
    }
}

// ----------------------------- entry ----------------------------------------
extern "C" void kernel_launch(void* const* d_in, const int* in_sizes, int n_in,
                              void* d_out, int out_size) {
    (void)in_sizes; (void)n_in; (void)out_size;
    cudaStream_t st = 0;

    const float* x  = (const float*)d_in[0];
    const void*  ei = d_in[1];
    const float* ew = (const float*)d_in[2];
    float* out = (float*)d_out;

    // prep: dtype detection + degrees + CSR build (by dst)
    k_detect<<<1, 32, 0, st>>>(ei);
    k_init_nodes<<<(NNODES + 255) / 256, 256, 0, st>>>();
    k_deg_hist<<<(NEDGES + 255) / 256, 256, 0, st>>>(ei, ew);
    k_dinv<<<(NNODES + 255) / 256, 256, 0, st>>>();
    k_scan<<<1, 1024, 0, st>>>();
    k_fill<<<(NEDGES + 255) / 256, 256, 0, st>>>(ei, ew);

    const int Cs[6] = {128, 64, 128, 256, 256, 128};
    const float* cur_ext = x;   // external pointer for layer input (x), else nullptr
    int cur_buf = -1;

    for (int li = 0; li < 5; li++) {
        int Cin = Cs[li], Cout = Cs[li + 1];
        const float* W  = (const float*)d_in[3 + 4 * li];
        const float* g  = (const float*)d_in[5 + 4 * li];
        const float* bb = (const float*)d_in[6 + 4 * li];

        dim3 grid((NNODES + GBM - 1) / GBM, Cout / GBN);
        if (Cin <= Cout) {
            // aggregate first (cheaper dim) into buf0, then GEMM -> buf1 (g_pre)
            launch_agg(cur_ext, cur_buf, 0, Cin, st);
            k_gemm<<<grid, 256, 0, st>>>(nullptr, 0, W, 1, NNODES, Cin, Cout);
        } else {
            // GEMM -> buf0, then aggregate (smaller output dim) -> buf1 (g_pre)
            k_gemm<<<grid, 256, 0, st>>>(cur_ext, cur_buf, W, 0, NNODES, Cin, Cout);
            launch_agg(nullptr, 0, 1, Cout, st);
        }

        // BatchNorm (+ ReLU except last layer). Bias b cancels under BN -> skipped.
        k_zero_stats<<<1, CMAX, 0, st>>>();
        k_bn_stats<<<(NNODES + 127) / 128, Cout, 0, st>>>(Cout);
        k_bn_final<<<1, CMAX, 0, st>>>(g, bb, Cout);

        int act_buf = (li & 1) ? 3 : 2;
        if (li == 4) launch_bn_apply(out, -1, Cout, false, st);
        else         launch_bn_apply(nullptr, act_buf, Cout, true, st);

        cur_ext = nullptr;
        cur_buf = act_buf;
    }
}